// round 5
// baseline (speedup 1.0000x reference)
#include <cuda_runtime.h>
#include <math.h>

#define TBITS 19
#define TMASK ((1u << TBITS) - 1u)
#define PRIME_Y 2654435761u
#define PRIME_Z 805459861u

typedef unsigned long long u64;

// ---- f32x2 packed helpers (FFMA2 is full-rate on sm_103a; 3-reg FFMA is half-rate) ----
__device__ __forceinline__ u64 ffma2(u64 a, u64 b, u64 c) {
    u64 d;
    asm("fma.rn.f32x2 %0, %1, %2, %3;" : "=l"(d) : "l"(a), "l"(b), "l"(c));
    return d;
}
__device__ __forceinline__ u64 pack2(float lo, float hi) {
    u64 d;
    asm("mov.b64 %0, {%1, %2};" : "=l"(d) : "f"(lo), "f"(hi));
    return d;
}
__device__ __forceinline__ float hadd2(u64 v) {
    float lo, hi;
    asm("mov.b64 {%0, %1}, %2;" : "=f"(lo), "=f"(hi) : "l"(v));
    return lo + hi;
}
__device__ __forceinline__ float lo2(u64 v) {
    float lo, hi;
    asm("mov.b64 {%0, %1}, %2;" : "=f"(lo), "=f"(hi) : "l"(v));
    return lo;
}

struct ResParams { float r[16]; };

__global__ __launch_bounds__(128, 3)
void ngp_fused_kernel(const float* __restrict__ positions,
                      const float* __restrict__ directions,
                      const float2* __restrict__ table,   // (16, 2^19, 2) fp32 -> float2
                      const float* __restrict__ W1,  const float* __restrict__ b1,
                      const float* __restrict__ W2,  const float* __restrict__ b2,
                      const float* __restrict__ Wc1, const float* __restrict__ bc1,
                      const float* __restrict__ Wc2, const float* __restrict__ bc2,
                      const float* __restrict__ Wc3, const float* __restrict__ bc3,
                      float* __restrict__ out, int n, ResParams rp)
{
    // Weights staged in shared, transposed so each output-neuron dot product
    // reads contiguous input-pairs via LDS.128 (two f32x2 operands per load).
    __shared__ __align__(16) float sW1T[64 * 32];   // [j][i]  (W1 is 32x64)
    __shared__ __align__(16) float sW2[64 * 16];    // [j][k]  (as given, 64x16)
    __shared__ __align__(16) float sWc1T[64 * 32];  // [j][i]  (Wc1 is 32x64)
    __shared__ __align__(16) float sWc2T[64 * 64];  // [j][k]  (Wc2 is 64x64, transposed)
    __shared__ __align__(16) float sWc3[64 * 4];    // [j][m], padded to 4 for aligned pair loads
    __shared__ __align__(16) float sB1[64];
    __shared__ __align__(16) float sB2[16];
    __shared__ __align__(16) float sBc1[64];
    __shared__ __align__(16) float sBc2[64];
    __shared__ __align__(16) float sBc3[4];

    const int tid = threadIdx.x;

    for (int t = tid; t < 2048; t += 128) sW1T[(t & 63) * 32 + (t >> 6)] = W1[t];
    for (int t = tid; t < 2048; t += 128) sWc1T[(t & 63) * 32 + (t >> 6)] = Wc1[t];
    for (int t = tid; t < 4096; t += 128) sWc2T[(t & 63) * 64 + (t >> 6)] = Wc2[t];
    for (int t = tid; t < 1024; t += 128) sW2[t] = W2[t];
    for (int t = tid; t < 192;  t += 128) sWc3[(t / 3) * 4 + (t % 3)] = Wc3[t];
    for (int t = tid; t < 64;   t += 128) { sB1[t] = b1[t]; sBc1[t] = bc1[t]; sBc2[t] = bc2[t]; }
    if (tid < 16) sB2[tid] = b2[tid];
    if (tid < 4)  sBc3[tid] = (tid < 3) ? bc3[tid] : 0.0f;
    __syncthreads();

    const int idx = blockIdx.x * 128 + tid;
    if (idx >= n) return;

    const float px = positions[idx * 3 + 0];
    const float py = positions[idx * 3 + 1];
    const float pz = positions[idx * 3 + 2];

    // ---------------- Hash-grid encode: enc as 16 packed (f0,f1) level pairs ----------------
    u64 enc2[16];
#pragma unroll
    for (int l = 0; l < 16; l++) {
        const float r = rp.r[l];
        const float sx = px * r, sy = py * r, sz = pz * r;
        const float fx = floorf(sx), fy = floorf(sy), fz = floorf(sz);
        const float tx = sx - fx, ty = sy - fy, tz = sz - fz;
        const unsigned ux = (unsigned)(int)fx;
        const unsigned uy = (unsigned)(int)fy;
        const unsigned uz = (unsigned)(int)fz;
        const unsigned x0 = ux,            x1 = ux + 1u;
        const unsigned y0 = uy * PRIME_Y,  y1 = y0 + PRIME_Y;
        const unsigned z0 = uz * PRIME_Z,  z1 = z0 + PRIME_Z;
        const unsigned base = ((unsigned)l) << TBITS;

        // issue all 8 gathers up front for MLP
        const float2 v000 = __ldg(&table[base + ((x0 ^ y0 ^ z0) & TMASK)]);
        const float2 v001 = __ldg(&table[base + ((x0 ^ y0 ^ z1) & TMASK)]);
        const float2 v010 = __ldg(&table[base + ((x0 ^ y1 ^ z0) & TMASK)]);
        const float2 v011 = __ldg(&table[base + ((x0 ^ y1 ^ z1) & TMASK)]);
        const float2 v100 = __ldg(&table[base + ((x1 ^ y0 ^ z0) & TMASK)]);
        const float2 v101 = __ldg(&table[base + ((x1 ^ y0 ^ z1) & TMASK)]);
        const float2 v110 = __ldg(&table[base + ((x1 ^ y1 ^ z0) & TMASK)]);
        const float2 v111 = __ldg(&table[base + ((x1 ^ y1 ^ z1) & TMASK)]);

        const float gx = 1.0f - tx, gy = 1.0f - ty, gz = 1.0f - tz;
        const float w00 = gx * gy, w01 = gx * ty, w10 = tx * gy, w11 = tx * ty;
        const float w000 = w00 * gz, w001 = w00 * tz;
        const float w010 = w01 * gz, w011 = w01 * tz;
        const float w100 = w10 * gz, w101 = w10 * tz;
        const float w110 = w11 * gz, w111 = w11 * tz;

        float alo = w000 * v000.x, ahi = w000 * v000.y;
        alo = fmaf(w001, v001.x, alo); ahi = fmaf(w001, v001.y, ahi);
        alo = fmaf(w010, v010.x, alo); ahi = fmaf(w010, v010.y, ahi);
        alo = fmaf(w011, v011.x, alo); ahi = fmaf(w011, v011.y, ahi);
        alo = fmaf(w100, v100.x, alo); ahi = fmaf(w100, v100.y, ahi);
        alo = fmaf(w101, v101.x, alo); ahi = fmaf(w101, v101.y, ahi);
        alo = fmaf(w110, v110.x, alo); ahi = fmaf(w110, v110.y, ahi);
        alo = fmaf(w111, v111.x, alo); ahi = fmaf(w111, v111.y, ahi);
        enc2[l] = pack2(alo, ahi);
    }

    // ---------------- Density MLP: h = relu(enc@W1+b1) streamed into feat = h@W2+b2 ----------------
    u64 featp[8];
#pragma unroll
    for (int q = 0; q < 8; q++) featp[q] = *(const u64*)&sB2[2 * q];

#pragma unroll 4
    for (int j = 0; j < 64; j++) {
        const ulonglong2* row = (const ulonglong2*)(sW1T + j * 32);
        u64 acc = 0ULL;
#pragma unroll
        for (int q = 0; q < 8; q++) {
            const ulonglong2 w = row[q];
            acc = ffma2(enc2[2 * q],     w.x, acc);
            acc = ffma2(enc2[2 * q + 1], w.y, acc);
        }
        float hj = hadd2(acc) + sB1[j];
        hj = fmaxf(hj, 0.0f);
        const u64 hd = pack2(hj, hj);
        const ulonglong2* r2 = (const ulonglong2*)(sW2 + j * 16);
#pragma unroll
        for (int q = 0; q < 4; q++) {
            const ulonglong2 w = r2[q];
            featp[2 * q]     = ffma2(hd, w.x, featp[2 * q]);
            featp[2 * q + 1] = ffma2(hd, w.y, featp[2 * q + 1]);
        }
    }
    const float density = expf(lo2(featp[0]));

    // ---------------- SH encode (degree 4, 16 coeffs) ----------------
    const float dx = directions[idx * 3 + 0];
    const float dy = directions[idx * 3 + 1];
    const float dz = directions[idx * 3 + 2];
    const float xx = dx * dx, yy = dy * dy, zz = dz * dz;

    u64 cinp[16];
#pragma unroll
    for (int q = 0; q < 8; q++) cinp[q] = featp[q];
    {
        const float s0  = 0.28209479177387814f;
        const float s1  = 0.4886025119029199f * dy;
        const float s2  = 0.4886025119029199f * dz;
        const float s3  = 0.4886025119029199f * dx;
        const float s4  = 1.0925484305920792f * dx * dy;
        const float s5  = 1.0925484305920792f * dy * dz;
        const float s6  = 0.9461746957575601f * zz - 0.31539156525252f;
        const float s7  = 1.0925484305920792f * dx * dz;
        const float s8  = 0.5462742152960396f * (xx - yy);
        const float s9  = 0.5900435899266435f * dy * (3.0f * xx - yy);
        const float s10 = 2.890611442640554f * dx * dy * dz;
        const float s11 = 0.4570457994644658f * dy * (5.0f * zz - 1.0f);
        const float s12 = 0.3731763325901154f * dz * (5.0f * zz - 3.0f);
        const float s13 = 0.4570457994644658f * dx * (5.0f * zz - 1.0f);
        const float s14 = 1.445305721320277f * dz * (xx - yy);
        const float s15 = 0.5900435899266435f * dx * (xx - 3.0f * yy);
        cinp[8]  = pack2(s0,  s1);
        cinp[9]  = pack2(s2,  s3);
        cinp[10] = pack2(s4,  s5);
        cinp[11] = pack2(s6,  s7);
        cinp[12] = pack2(s8,  s9);
        cinp[13] = pack2(s10, s11);
        cinp[14] = pack2(s12, s13);
        cinp[15] = pack2(s14, s15);
    }

    // ---------------- Color layer 1: c1 = relu(cin@Wc1+bc1), kept packed in pairs ----------------
    u64 c1p[32];
#pragma unroll
    for (int jp = 0; jp < 32; jp++) {
        const ulonglong2* rA = (const ulonglong2*)(sWc1T + (2 * jp) * 32);
        const ulonglong2* rB = (const ulonglong2*)(sWc1T + (2 * jp + 1) * 32);
        u64 a = 0ULL, b = 0ULL;
#pragma unroll
        for (int q = 0; q < 8; q++) {
            const ulonglong2 wa = rA[q];
            const ulonglong2 wb = rB[q];
            a = ffma2(cinp[2 * q],     wa.x, a);
            a = ffma2(cinp[2 * q + 1], wa.y, a);
            b = ffma2(cinp[2 * q],     wb.x, b);
            b = ffma2(cinp[2 * q + 1], wb.y, b);
        }
        const float ca = fmaxf(hadd2(a) + sBc1[2 * jp],     0.0f);
        const float cb = fmaxf(hadd2(b) + sBc1[2 * jp + 1], 0.0f);
        c1p[jp] = pack2(ca, cb);
    }

    // ---------------- Color layer 2 + output layer fused: rgb accumulates as c2 streams ----------------
    u64 rgb01 = *(const u64*)&sBc3[0];
    float rgb2 = sBc3[2];
#pragma unroll 4
    for (int j = 0; j < 64; j++) {
        const ulonglong2* row = (const ulonglong2*)(sWc2T + j * 64);
        u64 acc = 0ULL;
#pragma unroll
        for (int q = 0; q < 16; q++) {
            const ulonglong2 w = row[q];
            acc = ffma2(c1p[2 * q],     w.x, acc);
            acc = ffma2(c1p[2 * q + 1], w.y, acc);
        }
        const float c2j = fmaxf(hadd2(acc) + sBc2[j], 0.0f);
        const u64 cd = pack2(c2j, c2j);
        rgb01 = ffma2(cd, *(const u64*)&sWc3[j * 4], rgb01);
        rgb2 = fmaf(c2j, sWc3[j * 4 + 2], rgb2);
    }

    float r0, r1;
    asm("mov.b64 {%0, %1}, %2;" : "=f"(r0), "=f"(r1) : "l"(rgb01));
    r0 = 1.0f / (1.0f + expf(-r0));
    r1 = 1.0f / (1.0f + expf(-r1));
    const float r2s = 1.0f / (1.0f + expf(-rgb2));

    out[idx * 3 + 0] = r0;
    out[idx * 3 + 1] = r1;
    out[idx * 3 + 2] = r2s;
    out[3 * n + idx] = density;   // density concatenated after rgb
}

extern "C" void kernel_launch(void* const* d_in, const int* in_sizes, int n_in,
                              void* d_out, int out_size)
{
    const float*  positions  = (const float*)d_in[0];
    const float*  directions = (const float*)d_in[1];
    const float2* table      = (const float2*)d_in[2];
    const float*  W1  = (const float*)d_in[3];
    const float*  b1  = (const float*)d_in[4];
    const float*  W2  = (const float*)d_in[5];
    const float*  b2  = (const float*)d_in[6];
    const float*  Wc1 = (const float*)d_in[7];
    const float*  bc1 = (const float*)d_in[8];
    const float*  Wc2 = (const float*)d_in[9];
    const float*  bc2 = (const float*)d_in[10];
    const float*  Wc3 = (const float*)d_in[11];
    const float*  bc3 = (const float*)d_in[12];
    float* out = (float*)d_out;

    const int n = in_sizes[0] / 3;

    // Resolutions must match numpy's float64 computation exactly (level 7 is
    // 153.987 -> 153; level 15 sits within 1e-11 of 2048). Replicate the same
    // libm double-precision exp/log/pow chain numpy uses.
    ResParams rp;
    const double bb = exp((log(2048.0) - log(16.0)) / 15.0);
    for (int l = 0; l < 16; l++)
        rp.r[l] = (float)floor(16.0 * pow(bb, (double)l));

    const int block = 128;
    const int grid = (n + block - 1) / block;
    ngp_fused_kernel<<<grid, block>>>(positions, directions, table,
                                      W1, b1, W2, b2, Wc1, bc1, Wc2, bc2, Wc3, bc3,
                                      out, n, rp);
}